// round 2
// baseline (speedup 1.0000x reference)
#include <cuda_runtime.h>
#include <math.h>

#define NROW 8192
#define ALPHA 0.2f
#define NEGV -9e15f

// packed fp32x2 FMA (Blackwell): d = a*b + d, lanewise on 2 packed floats
#define FMA_F32X2(d, a, b) \
  asm("fma.rn.f32x2 %0, %1, %2, %0;" : "+l"(d) : "l"(a), "l"(b))
#define UNPACK_F32X2(lo, hi, v) \
  asm("mov.b64 {%0, %1}, %2;" : "=f"(lo), "=f"(hi) : "l"(v))

// ---- scratch (static device globals; no allocation) ----
__device__ __align__(16) float g_h1[NROW * 256];   // layer1 linear out
__device__ __align__(16) float g_x2[NROW * 256];   // elu(elu(attn1 @ h1))
__device__ __align__(16) float g_h2[NROW * 64];    // layer2 linear out
__device__ float g_hl[NROW];
__device__ float g_hr[NROW];
__device__ float g_mrow[NROW];
__device__ float g_sinv[NROW];

__device__ __forceinline__ float elu1(float z) { return z > 0.f ? z : expm1f(z); }

// ============================================================================
// C[M,Fd] = A[M,K] @ W[Fd,K]^T + b      (64x64 tile, 4x4 per thread)
// ============================================================================
__global__ void __launch_bounds__(256) gemm_bias_k(
    const float* __restrict__ A, const float* __restrict__ W,
    const float* __restrict__ b, float* __restrict__ C, int K, int Fd) {
  __shared__ float As[64][17];
  __shared__ float Ws[64][17];
  int tid = threadIdx.x;
  int tx = tid & 15, ty = tid >> 4;
  int mbase = blockIdx.y * 64, fbase = blockIdx.x * 64;
  float acc[4][4] = {};
  for (int k0 = 0; k0 < K; k0 += 16) {
#pragma unroll
    for (int idx = tid; idx < 1024; idx += 256) {
      int r = idx >> 4, k = idx & 15;
      As[r][k] = A[(size_t)(mbase + r) * K + k0 + k];
      Ws[r][k] = W[(size_t)(fbase + r) * K + k0 + k];
    }
    __syncthreads();
#pragma unroll
    for (int k = 0; k < 16; k++) {
      float a[4], w[4];
#pragma unroll
      for (int r = 0; r < 4; r++) a[r] = As[ty * 4 + r][k];
#pragma unroll
      for (int c = 0; c < 4; c++) w[c] = Ws[tx * 4 + c][k];
#pragma unroll
      for (int r = 0; r < 4; r++)
#pragma unroll
        for (int c = 0; c < 4; c++) acc[r][c] += a[r] * w[c];
    }
    __syncthreads();
  }
#pragma unroll
  for (int r = 0; r < 4; r++) {
    int row = mbase + ty * 4 + r;
#pragma unroll
    for (int c = 0; c < 4; c++) {
      int col = fbase + tx * 4 + c;
      C[(size_t)row * Fd + col] = acc[r][c] + b[col];
    }
  }
}

// ============================================================================
// hl[i] = dot(h[i,:], a[0:F]);  hr[i] = dot(h[i,:], a[F:2F])
// ============================================================================
__global__ void __launch_bounds__(256) attn_vec_k(
    const float* __restrict__ h, const float* __restrict__ a, int Fd,
    float* __restrict__ hl, float* __restrict__ hr) {
  int i = blockIdx.x, t = threadIdx.x;
  float pl = 0.f, pr = 0.f;
  if (t < Fd) {
    float x = h[(size_t)i * Fd + t];
    pl = x * a[t];
    pr = x * a[Fd + t];
  }
  __shared__ float sl[256], sr[256];
  sl[t] = pl; sr[t] = pr;
  __syncthreads();
  for (int s = 128; s > 0; s >>= 1) {
    if (t < s) { sl[t] += sl[t + s]; sr[t] += sr[t + s]; }
    __syncthreads();
  }
  if (t == 0) { hl[i] = sl[0]; hr[i] = sr[0]; }
}

// ============================================================================
// per-row online softmax stats over masked scores
// ============================================================================
__device__ __forceinline__ void online_upd(float v, float& m, float& s) {
  if (v <= m) {
    s += __expf(v - m);
  } else {
    s = s * __expf(m - v) + 1.f;
    m = v;
  }
}

__global__ void __launch_bounds__(256) softmax_stats_k(
    const int* __restrict__ adj, const float* __restrict__ hr,
    const float* __restrict__ hl, const float* __restrict__ ab,
    float* __restrict__ mrow, float* __restrict__ sinv) {
  int i = blockIdx.x, t = threadIdx.x;
  float hli = hl[i] + ab[0];
  const int4* adj4 = (const int4*)(adj + (size_t)i * NROW);
  const float4* hr4 = (const float4*)hr;
  float m = -INFINITY, s = 0.f;
  for (int j = t; j < NROW / 4; j += 256) {
    int4 av = adj4[j];
    float4 hv = hr4[j];
    float e, v;
    e = hli + hv.x; e = e > 0.f ? e : ALPHA * e; v = av.x ? e : NEGV; online_upd(v, m, s);
    e = hli + hv.y; e = e > 0.f ? e : ALPHA * e; v = av.y ? e : NEGV; online_upd(v, m, s);
    e = hli + hv.z; e = e > 0.f ? e : ALPHA * e; v = av.z ? e : NEGV; online_upd(v, m, s);
    e = hli + hv.w; e = e > 0.f ? e : ALPHA * e; v = av.w ? e : NEGV; online_upd(v, m, s);
  }
  __shared__ float sm[256], ss[256];
  sm[t] = m; ss[t] = s;
  __syncthreads();
  for (int st = 128; st > 0; st >>= 1) {
    if (t < st) {
      float m2 = sm[t + st], s2 = ss[t + st];
      float M = fmaxf(sm[t], m2);
      ss[t] = ss[t] * __expf(sm[t] - M) + s2 * __expf(m2 - M);
      sm[t] = M;
    }
    __syncthreads();
  }
  if (t == 0) { mrow[i] = sm[0]; sinv[i] = 1.f / ss[0]; }
}

// ============================================================================
// out[MT rows, F cols] = softmax-weights (recomputed on the fly) @ h + epilogue
// packed f32x2 inner loop (FFMA2). ws duplicated as (w,w) float2 so weights
// arrive pre-packed via a single LDS.128 per 2 rows.
// EPI==1 : elu(elu(.)) -> x2     EPI==2 : elu(.) -> out (log_softmax later)
// ============================================================================
template <int F, int MT, int EPI>
__global__ void __launch_bounds__(256, 2) attn_gemm_k(
    const int* __restrict__ adj, const float* __restrict__ h,
    const float* __restrict__ hl, const float* __restrict__ hr,
    const float* __restrict__ ab, const float* __restrict__ mrow,
    const float* __restrict__ sinv, float* __restrict__ out) {
  constexpr int KC = 32;
  constexpr int CG = F / 4;              // float4 column groups
  constexpr int IG = 256 / CG;           // i-groups
  constexpr int IPT = MT / IG;           // rows per thread (even; acc pairs)
  constexpr int WPT = (MT * KC) / 1024;  // rows per thread in w-phase
  constexpr int HPT = (KC * F / 4) / 256;  // float4 per thread for h chunk
  __shared__ __align__(16) float hs[KC][F];
  __shared__ __align__(16) float2 ws2[KC][MT + 2];  // (w,w) dup; stride %16==0

  int tid = threadIdx.x;
  int ibase = blockIdx.x * MT;
  int cg = tid % CG, ig = tid / CG;
  int iw = tid >> 3;                   // base row for w-phase
  int jw = (tid & 7) * 4;              // k offset within chunk

  float hli[WPT], mi[WPT], si[WPT];
#pragma unroll
  for (int w = 0; w < WPT; w++) {
    int row = ibase + iw + w * 32;
    hli[w] = hl[row] + ab[0];
    mi[w] = mrow[row];
    si[w] = sinv[row];
  }

  const float4* h4 = (const float4*)h;
  unsigned long long acc2[IPT][2] = {};  // packed (f32,f32) accumulators

  for (int k0 = 0; k0 < NROW; k0 += KC) {
    // global loads into registers BEFORE the barrier: overlap previous
    // chunk's FMA phase with L2/DRAM latency.
    float4 hreg[HPT];
#pragma unroll
    for (int t = 0; t < HPT; t++) {
      int idx = tid + t * 256;
      hreg[t] = h4[(size_t)(k0 + idx / (F / 4)) * (F / 4) + idx % (F / 4)];
    }
    int4 av[WPT];
#pragma unroll
    for (int w = 0; w < WPT; w++)
      av[w] = *(const int4*)(adj + (size_t)(ibase + iw + w * 32) * NROW + k0 + jw);
    float4 hrv = *(const float4*)(hr + k0 + jw);

    __syncthreads();  // previous chunk's FMA done; smem free
#pragma unroll
    for (int t = 0; t < HPT; t++) {
      int idx = tid + t * 256;
      ((float4*)&hs[idx / (F / 4)][0])[idx % (F / 4)] = hreg[t];
    }
#pragma unroll
    for (int w = 0; w < WPT; w++) {
      int i = iw + w * 32;
      float e, v, wv;
      e = hli[w] + hrv.x; e = e > 0.f ? e : ALPHA * e; v = av[w].x ? e : NEGV;
      wv = __expf(v - mi[w]) * si[w]; ws2[jw + 0][i] = make_float2(wv, wv);
      e = hli[w] + hrv.y; e = e > 0.f ? e : ALPHA * e; v = av[w].y ? e : NEGV;
      wv = __expf(v - mi[w]) * si[w]; ws2[jw + 1][i] = make_float2(wv, wv);
      e = hli[w] + hrv.z; e = e > 0.f ? e : ALPHA * e; v = av[w].z ? e : NEGV;
      wv = __expf(v - mi[w]) * si[w]; ws2[jw + 2][i] = make_float2(wv, wv);
      e = hli[w] + hrv.w; e = e > 0.f ? e : ALPHA * e; v = av[w].w ? e : NEGV;
      wv = __expf(v - mi[w]) * si[w]; ws2[jw + 3][i] = make_float2(wv, wv);
    }
    __syncthreads();

#pragma unroll
    for (int k = 0; k < KC; k++) {
      // one LDS.128: 4 h-columns as 2 packed f32x2
      ulonglong2 hp = ((const ulonglong2*)&hs[k][0])[cg];
#pragma unroll
      for (int r2 = 0; r2 < IPT / 2; r2++) {
        // one LDS.128 broadcast: weights for rows 2*r2 and 2*r2+1, pre-dup'd
        ulonglong2 wp =
            ((const ulonglong2*)&ws2[k][0])[ig * (IPT / 2) + r2];
        FMA_F32X2(acc2[2 * r2 + 0][0], wp.x, hp.x);
        FMA_F32X2(acc2[2 * r2 + 0][1], wp.x, hp.y);
        FMA_F32X2(acc2[2 * r2 + 1][0], wp.y, hp.x);
        FMA_F32X2(acc2[2 * r2 + 1][1], wp.y, hp.y);
      }
    }
  }

#pragma unroll
  for (int r = 0; r < IPT; r++) {
    int row = ibase + ig * IPT + r;
    float* op = out + (size_t)row * F + cg * 4;
    float z[4];
    UNPACK_F32X2(z[0], z[1], acc2[r][0]);
    UNPACK_F32X2(z[2], z[3], acc2[r][1]);
#pragma unroll
    for (int q = 0; q < 4; q++) {
      float y = z[q];
      if (EPI == 1) y = elu1(elu1(y));
      else          y = elu1(y);
      op[q] = y;
    }
  }
}

// ============================================================================
// in-place log_softmax over 64-wide rows; one warp per row
// ============================================================================
__global__ void __launch_bounds__(256) log_softmax64_k(float* __restrict__ o) {
  int warp = (blockIdx.x * blockDim.x + threadIdx.x) >> 5;
  int lane = threadIdx.x & 31;
  float* row = o + (size_t)warp * 64;
  float v0 = row[lane], v1 = row[lane + 32];
  float m = fmaxf(v0, v1);
#pragma unroll
  for (int s = 16; s > 0; s >>= 1) m = fmaxf(m, __shfl_xor_sync(0xFFFFFFFFu, m, s));
  float s = __expf(v0 - m) + __expf(v1 - m);
#pragma unroll
  for (int st = 16; st > 0; st >>= 1) s += __shfl_xor_sync(0xFFFFFFFFu, s, st);
  float l = m + logf(s);
  row[lane] = v0 - l;
  row[lane + 32] = v1 - l;
}

// ============================================================================
extern "C" void kernel_launch(void* const* d_in, const int* in_sizes, int n_in,
                              void* d_out, int out_size) {
  const float* x   = (const float*)d_in[0];
  const int*   adj = (const int*)d_in[1];
  const float* W1  = (const float*)d_in[2];
  const float* b1  = (const float*)d_in[3];
  const float* a1  = (const float*)d_in[4];
  const float* ab1 = (const float*)d_in[5];
  const float* W2  = (const float*)d_in[6];
  const float* b2  = (const float*)d_in[7];
  const float* a2  = (const float*)d_in[8];
  const float* ab2 = (const float*)d_in[9];
  float* out = (float*)d_out;

  float *h1, *x2, *h2, *hl, *hr, *mr, *si;
  cudaGetSymbolAddress((void**)&h1, g_h1);
  cudaGetSymbolAddress((void**)&x2, g_x2);
  cudaGetSymbolAddress((void**)&h2, g_h2);
  cudaGetSymbolAddress((void**)&hl, g_hl);
  cudaGetSymbolAddress((void**)&hr, g_hr);
  cudaGetSymbolAddress((void**)&mr, g_mrow);
  cudaGetSymbolAddress((void**)&si, g_sinv);

  // ---- layer 1 ----
  gemm_bias_k<<<dim3(256 / 64, NROW / 64), 256>>>(x, W1, b1, h1, 512, 256);
  attn_vec_k<<<NROW, 256>>>(h1, a1, 256, hl, hr);
  softmax_stats_k<<<NROW, 256>>>(adj, hr, hl, ab1, mr, si);
  attn_gemm_k<256, 32, 1><<<NROW / 32, 256>>>(adj, h1, hl, hr, ab1, mr, si, x2);

  // ---- layer 2 ----
  gemm_bias_k<<<dim3(64 / 64, NROW / 64), 256>>>(x2, W2, b2, h2, 256, 64);
  attn_vec_k<<<NROW, 256>>>(h2, a2, 64, hl, hr);
  softmax_stats_k<<<NROW, 256>>>(adj, hr, hl, ab2, mr, si);
  attn_gemm_k<64, 64, 2><<<NROW / 64, 256>>>(adj, h2, hl, hr, ab2, mr, si, out);

  // ---- final log_softmax (in place on d_out) ----
  log_softmax64_k<<<NROW / 8, 256>>>(out);
}